// round 5
// baseline (speedup 1.0000x reference)
#include <cuda_runtime.h>
#include <math.h>

#define VV 4
#define NN 2048
#define DD 128
#define KK 10
#define NPAIR 12
#define CAND_CAP 64
#define PROJ_BLOCKS 768    // 12 mats x 64 tiles (32 rows each)
#define TOPK_BLOCKS 6144   // 24576 rows / 4 per block
#define TOTAL_BLOCKS (PROJ_BLOCKS + TOPK_BLOCKS)   // 6912, 1:8 interleave

// ---------------- scratch (no allocs allowed) ----------------
__device__ float g_Q[VV * NN * DD];
__device__ float g_K[VV * NN * DD];
__device__ float g_V[VV * NN * DD];
__device__ int   g_idx[NPAIR * NN * KK];
__device__ float4 g_meanV4[VV * (DD / 4)];

// total-order 64-bit key: higher value wins; ties -> lower index (matches lax.top_k)
// C >= 0 so monotonic mapping is just bits | signbit
__device__ __forceinline__ unsigned long long tk_key(float x, int m)
{
    unsigned int mb = __float_as_uint(x) | 0x80000000u;
    return ((unsigned long long)mb << 32) | (unsigned int)(NN - 1 - m);
}

__device__ __forceinline__ unsigned long long wmax64(unsigned long long k)
{
#pragma unroll
    for (int off = 16; off > 0; off >>= 1) {
        unsigned long long o = __shfl_xor_sync(0xffffffffu, k, off);
        if (o > k) k = o;
    }
    return k;
}

struct ProjS {
    float Xs[32][16];
    float Ws[16][132];
};
struct TopkS {
    float4 rb[4][512];                    // 4 rows x 2048 floats (32 KB)
    unsigned long long cbuf[4][CAND_CAP]; // 2 KB
};

// ================= fused proj (+meanV) + topk =================
__global__ __launch_bounds__(128, 6) void proj_topk_kernel(
    const float* __restrict__ aligned,
    const float* __restrict__ WQ,
    const float* __restrict__ WK,
    const float* __restrict__ WV,
    const float* __restrict__ C)
{
    __shared__ __align__(16) unsigned char smem_raw[sizeof(TopkS)];
    int bid = blockIdx.x;
    int tid = threadIdx.x;
    int warp = tid >> 5, lane = tid & 31;

    if (bid % 9 == 0) {
        // ---------------- projection GEMM block: 32 rows x 128 cols ----------------
        ProjS& S = *reinterpret_cast<ProjS*>(smem_raw);
        int pb = bid / 9;                 // 0..767
        int tile = pb & 63;
        int vm   = pb >> 6;               // 0..11
        int v = vm / 3, mat = vm % 3;
        const float* W = (mat == 0 ? WQ : (mat == 1 ? WK : WV)) + (size_t)v * DD * DD;
        float* Out = (mat == 0 ? g_Q : (mat == 1 ? g_K : g_V))
                     + (size_t)v * NN * DD + (size_t)tile * 32 * DD;
        const float* X = aligned + (size_t)v * NN * DD + (size_t)tile * 32 * DD;

        float acc[8][4];
#pragma unroll
        for (int i = 0; i < 8; ++i)
#pragma unroll
            for (int c = 0; c < 4; ++c) acc[i][c] = 0.f;

        for (int d0 = 0; d0 < DD; d0 += 16) {
            {
                int r = tid >> 2, f = tid & 3;
                float4 xv = *(const float4*)(X + (size_t)r * DD + d0 + f * 4);
                *(float4*)&S.Xs[r][f * 4] = xv;
            }
#pragma unroll
            for (int j = 0; j < 4; ++j) {
                int lin = tid * 4 + j;
                int e = lin >> 2, f = lin & 3;
                float4 wv = *(const float4*)(W + (size_t)e * DD + d0 + f * 4);
                S.Ws[f * 4 + 0][e] = wv.x;
                S.Ws[f * 4 + 1][e] = wv.y;
                S.Ws[f * 4 + 2][e] = wv.z;
                S.Ws[f * 4 + 3][e] = wv.w;
            }
            __syncthreads();
#pragma unroll
            for (int dd = 0; dd < 16; ++dd) {
                float4 b = *(const float4*)&S.Ws[dd][lane * 4];
#pragma unroll
                for (int i = 0; i < 8; ++i) {
                    float a = S.Xs[warp * 8 + i][dd];
                    acc[i][0] += a * b.x;
                    acc[i][1] += a * b.y;
                    acc[i][2] += a * b.z;
                    acc[i][3] += a * b.w;
                }
            }
            __syncthreads();
        }
#pragma unroll
        for (int i = 0; i < 8; ++i) {
            float4 o = make_float4(acc[i][0], acc[i][1], acc[i][2], acc[i][3]);
            *(float4*)(Out + (size_t)(warp * 8 + i) * DD + lane * 4) = o;
        }
        if (mat == 2) {
#pragma unroll
            for (int c = 0; c < 4; ++c) {
                float s = 0.f;
#pragma unroll
                for (int i = 0; i < 8; ++i) s += acc[i][c];
                atomicAdd((float*)&g_meanV4[0] + v * DD + lane * 4 + c, s);
            }
        }
        return;
    }

    // ---------------- topk block: 4 warps, one row each, smem-staged ----------------
    TopkS& S = *reinterpret_cast<TopkS*>(smem_raw);
    int tb = bid - bid / 9 - 1;           // 0..6143
    int rowg = tb * 4 + warp;             // 0..24575
    int pair = rowg / NN, n = rowg % NN;
    int p = pair / 3, qm = pair % 3;
    int q = qm + (qm >= p ? 1 : 0);
    const float4* rowp4 = (const float4*)
        (C + (((size_t)p * VV + q) * NN + n) * (size_t)NN);

    // pass 1: stream row -> smem, track per-lane float max
    float mx = -3.4e38f;
#pragma unroll
    for (int i = 0; i < 16; ++i) {
        float4 v = __ldcs(rowp4 + lane + (i << 5));
        S.rb[warp][lane + (i << 5)] = v;
        mx = fmaxf(mx, fmaxf(fmaxf(v.x, v.y), fmaxf(v.z, v.w)));
    }

    // tau = (<=10th)-largest lane max (duplicate retire only lowers tau -> safe)
    float cur = mx;
    float tau = 0.f;
#pragma unroll
    for (int r = 0; r < KK; ++r) {
        float m = cur;
#pragma unroll
        for (int off = 16; off > 0; off >>= 1)
            m = fmaxf(m, __shfl_xor_sync(0xffffffffu, m, off));
        if (cur == m) cur = -3.4e38f;
        tau = m;
    }

    // pass 2: from smem, count-per-chunk + prefix-scan compaction
    int base = 0;
#pragma unroll
    for (int c = 0; c < 4; ++c) {
        float4 vv[4];
#pragma unroll
        for (int i = 0; i < 4; ++i) vv[i] = S.rb[warp][lane + ((c * 4 + i) << 5)];
        int cnt = 0;
#pragma unroll
        for (int i = 0; i < 4; ++i) {
            cnt += (vv[i].x >= tau); cnt += (vv[i].y >= tau);
            cnt += (vv[i].z >= tau); cnt += (vv[i].w >= tau);
        }
        int inc = cnt;
#pragma unroll
        for (int off = 1; off < 32; off <<= 1) {
            int t = __shfl_up_sync(0xffffffffu, inc, off);
            if (lane >= off) inc += t;
        }
        int wpos = base + inc - cnt;
        int total = __shfl_sync(0xffffffffu, inc, 31);
        if (cnt) {
#pragma unroll
            for (int i = 0; i < 4; ++i) {
                int mb = (lane + ((c * 4 + i) << 5)) << 2;
                float e[4] = {vv[i].x, vv[i].y, vv[i].z, vv[i].w};
#pragma unroll
                for (int k = 0; k < 4; ++k) {
                    if (e[k] >= tau) {
                        if (wpos < CAND_CAP) S.cbuf[warp][wpos] = tk_key(e[k], mb + k);
                        wpos++;
                    }
                }
            }
        }
        base += total;
    }
    __syncwarp();

    int* outp = g_idx + (size_t)rowg * KK;
    if (base <= CAND_CAP) {
        unsigned long long a = (lane < base) ? S.cbuf[warp][lane] : 0ull;
        unsigned long long b = (lane + 32 < base) ? S.cbuf[warp][lane + 32] : 0ull;
        unsigned long long cand = (a > b) ? a : b;
#pragma unroll
        for (int r = 0; r < KK; ++r) {
            unsigned long long m = wmax64(cand);
            if (lane == 0) outp[r] = NN - 1 - (int)(m & 0xffffffffu);
            if (cand == m) {
                if (a == m) a = 0ull; else b = 0ull;
                cand = (a > b) ? a : b;
            }
        }
    } else {
        // exact fallback: bounded rescan from smem (pathological ties only)
        unsigned long long bound = ~0ull;
        for (int r = 0; r < KK; ++r) {
            unsigned long long candk = 0ull;
            for (int i = 0; i < 16; ++i) {
                float4 v = S.rb[warp][lane + (i << 5)];
                int mb = (lane + (i << 5)) << 2;
                unsigned long long k;
                k = tk_key(v.x, mb + 0); if (k < bound && k > candk) candk = k;
                k = tk_key(v.y, mb + 1); if (k < bound && k > candk) candk = k;
                k = tk_key(v.z, mb + 2); if (k < bound && k > candk) candk = k;
                k = tk_key(v.w, mb + 3); if (k < bound && k > candk) candk = k;
            }
            unsigned long long m = wmax64(candk);
            if (lane == 0) outp[r] = NN - 1 - (int)(m & 0xffffffffu);
            bound = m;
        }
    }
}

// ---------------- gather + sparse softmax + aggregate (vectorized) ----------------
__global__ __launch_bounds__(128) void gather_kernel(float* __restrict__ out)
{
    int n = blockIdx.x, p = blockIdx.y;
    int tid = threadIdx.x;
    int w = tid >> 5, lane = tid & 31;

    __shared__ float4 qs4[32];
    __shared__ int    sidx[32];
    __shared__ float  sc[32];
    __shared__ float  sw[32];
    __shared__ float  smax[4], ssum[4];
    __shared__ float4 part[4][32];

    if (w == 0)
        qs4[lane] = ((const float4*)g_Q)[((size_t)p * NN + n) * 32 + lane];
    if (tid >= 32 && tid < 32 + 3 * KK) {
        int t = tid - 32;
        int pair = p * 3 + t / KK;
        sidx[t] = g_idx[((size_t)pair * NN + n) * KK + (t % KK)];
    }
    __syncthreads();

    // 30 dots: one LDG.128 per warp per row
    float4 q4 = qs4[lane];
    for (int t = w; t < 3 * KK; t += 4) {
        int qm = t / KK;
        int q = qm + (qm >= p ? 1 : 0);
        int m = sidx[t];
        float4 k4 = __ldg(((const float4*)g_K) + ((size_t)q * NN + m) * 32 + lane);
        float s = q4.x * k4.x + q4.y * k4.y + q4.z * k4.z + q4.w * k4.w;
#pragma unroll
        for (int off = 16; off > 0; off >>= 1)
            s += __shfl_xor_sync(0xffffffffu, s, off);
        if (lane == 0) sc[t] = s * 0.08838834764831845f;
    }
    __syncthreads();

    if (tid < 3) {
        float m2 = -3.4e38f;
#pragma unroll
        for (int k = 0; k < KK; ++k) m2 = fmaxf(m2, sc[tid * KK + k]);
        smax[tid] = m2;
    }
    __syncthreads();
    if (tid < 3 * KK) sc[tid] = expf(sc[tid] - smax[tid / KK]);
    __syncthreads();
    if (tid < 3) {
        float su = 0.f;
#pragma unroll
        for (int k = 0; k < KK; ++k) su += sc[tid * KK + k];
        ssum[tid] = su;
    }
    __syncthreads();
    if (tid < 3 * KK) sw[tid] = sc[tid] / ssum[tid / KK];
    __syncthreads();

    // epilogue: warp w accumulates rows t = w, w+4, ...
    float4 acc = make_float4(0.f, 0.f, 0.f, 0.f);
    for (int t = w; t < 3 * KK; t += 4) {
        int qm = t / KK;
        int q = qm + (qm >= p ? 1 : 0);
        float4 v4 = __ldg(((const float4*)g_V) + ((size_t)q * NN + sidx[t]) * 32 + lane);
        float wt = sw[t];
        acc.x += wt * v4.x; acc.y += wt * v4.y;
        acc.z += wt * v4.z; acc.w += wt * v4.w;
    }
    part[w][lane] = acc;
    __syncthreads();

    if (w == 0) {
        float4 a0 = part[0][lane], a1 = part[1][lane];
        float4 a2 = part[2][lane], a3 = part[3][lane];
        float4 mv = g_meanV4[p * 32 + lane];
        const float inv = 1.0f / NN;
        float4 o;
        o.x = a0.x + a1.x + a2.x + a3.x + mv.x * inv;
        o.y = a0.y + a1.y + a2.y + a3.y + mv.y * inv;
        o.z = a0.z + a1.z + a2.z + a3.z + mv.z * inv;
        o.w = a0.w + a1.w + a2.w + a3.w + mv.w * inv;
        ((float4*)out)[((size_t)p * NN + n) * 32 + lane] = o;
    }
}

// ---------------- launch ----------------
extern "C" void kernel_launch(void* const* d_in, const int* in_sizes, int n_in,
                              void* d_out, int out_size)
{
    const float* aligned = (const float*)d_in[0];
    const float* C       = (const float*)d_in[1];
    const float* WQ      = (const float*)d_in[2];
    const float* WK      = (const float*)d_in[3];
    const float* WV      = (const float*)d_in[4];
    float* out = (float*)d_out;

    void* meanp = nullptr;
    cudaGetSymbolAddress(&meanp, g_meanV4);

    cudaMemsetAsync(meanp, 0, VV * DD * sizeof(float));
    proj_topk_kernel<<<TOTAL_BLOCKS, 128>>>(aligned, WQ, WK, WV, C);
    gather_kernel<<<dim3(NN, VV), 128>>>(out);
}

// round 6
// speedup vs baseline: 1.0738x; 1.0738x over previous
#include <cuda_runtime.h>
#include <math.h>

#define VV 4
#define NN 2048
#define DD 128
#define KK 10
#define NPAIR 12
#define CAP 160            // candidate key slots per row (40 chunks x 4)
#define TAU0 0.99f         // static threshold; exact fallback covers any input
#define PROJ_BLOCKS 384
#define TOPK_BLOCKS 1536   // 16 rows per block (8 warps x 2 rows)
#define TOTAL_BLOCKS (PROJ_BLOCKS + TOPK_BLOCKS)   // 1920, 1:4 interleave

// ---------------- scratch (no allocs allowed) ----------------
__device__ float g_Q[VV * NN * DD];
__device__ float g_K[VV * NN * DD];
__device__ float g_V[VV * NN * DD];
__device__ int   g_idx[NPAIR * NN * KK];
__device__ float4 g_meanV4[VV * (DD / 4)];

// total-order 64-bit key: higher value wins; ties -> lower index (matches
// lax.top_k). C >= 0 so monotonic float map is bits | signbit.
__device__ __forceinline__ unsigned long long tk_key(float x, int m)
{
    unsigned int mb = __float_as_uint(x) | 0x80000000u;
    return ((unsigned long long)mb << 32) | (unsigned int)(NN - 1 - m);
}

__device__ __forceinline__ unsigned long long wmax64(unsigned long long k)
{
#pragma unroll
    for (int off = 16; off > 0; off >>= 1) {
        unsigned long long o = __shfl_xor_sync(0xffffffffu, k, off);
        if (o > k) k = o;
    }
    return k;
}

struct ProjS {
    float Xs[64][16];
    float Ws[16][132];
};
struct TopkS {
    unsigned long long cbuf[8][2][CAP];   // 20 KB
};

// exact bounded-rescan fallback (rare): 10 extraction rounds over the row
__device__ void topk_fallback(const float4* __restrict__ rp4, int lane, int* outp)
{
    unsigned long long bound = ~0ull;
    for (int r = 0; r < KK; ++r) {
        unsigned long long cand = 0ull;
        for (int i = 0; i < 16; ++i) {
            float4 v = rp4[lane + (i << 5)];
            int mb = (lane + (i << 5)) << 2;
            unsigned long long k;
            k = tk_key(v.x, mb + 0); if (k < bound && k > cand) cand = k;
            k = tk_key(v.y, mb + 1); if (k < bound && k > cand) cand = k;
            k = tk_key(v.z, mb + 2); if (k < bound && k > cand) cand = k;
            k = tk_key(v.w, mb + 3); if (k < bound && k > cand) cand = k;
        }
        unsigned long long m = wmax64(cand);
        if (lane == 0) outp[r] = NN - 1 - (int)(m & 0xffffffffu);
        bound = m;
    }
}

// ================= fused proj + topk =================
__global__ __launch_bounds__(256, 4) void proj_topk_kernel(
    const float* __restrict__ aligned,
    const float* __restrict__ WQ,
    const float* __restrict__ WK,
    const float* __restrict__ WV,
    const float* __restrict__ C)
{
    __shared__ __align__(16) unsigned char smem_raw[sizeof(TopkS)];
    int bid = blockIdx.x;
    int tid = threadIdx.x;
    int warp = tid >> 5, lane = tid & 31;

    if (bid % 5 == 0) {
        // ---------------- projection GEMM: 64 rows x 128 cols ----------------
        ProjS& S = *reinterpret_cast<ProjS*>(smem_raw);
        int pb = bid / 5;                 // 0..383
        int tile = pb & 31;
        int vm   = pb >> 5;               // 0..11
        int v = vm / 3, mat = vm % 3;
        const float* W = (mat == 0 ? WQ : (mat == 1 ? WK : WV)) + (size_t)v * DD * DD;
        float* Out = (mat == 0 ? g_Q : (mat == 1 ? g_K : g_V))
                     + (size_t)v * NN * DD + (size_t)tile * 64 * DD;
        const float* X = aligned + (size_t)v * NN * DD + (size_t)tile * 64 * DD;

        float acc[8][4];
#pragma unroll
        for (int i = 0; i < 8; ++i)
#pragma unroll
            for (int c = 0; c < 4; ++c) acc[i][c] = 0.f;

        for (int d0 = 0; d0 < DD; d0 += 16) {
            {
                int r = tid >> 2, f = tid & 3;
                float4 xv = *(const float4*)(X + (size_t)r * DD + d0 + f * 4);
                *(float4*)&S.Xs[r][f * 4] = xv;
            }
#pragma unroll
            for (int j = 0; j < 2; ++j) {
                int lin = tid * 2 + j;
                int e = lin >> 2, f = lin & 3;
                float4 wv = *(const float4*)(W + (size_t)e * DD + d0 + f * 4);
                S.Ws[f * 4 + 0][e] = wv.x;
                S.Ws[f * 4 + 1][e] = wv.y;
                S.Ws[f * 4 + 2][e] = wv.z;
                S.Ws[f * 4 + 3][e] = wv.w;
            }
            __syncthreads();
#pragma unroll
            for (int dd = 0; dd < 16; ++dd) {
                float4 b = *(const float4*)&S.Ws[dd][lane * 4];
#pragma unroll
                for (int i = 0; i < 8; ++i) {
                    float a = S.Xs[warp * 8 + i][dd];
                    acc[i][0] += a * b.x;
                    acc[i][1] += a * b.y;
                    acc[i][2] += a * b.z;
                    acc[i][3] += a * b.w;
                }
            }
            __syncthreads();
        }
#pragma unroll
        for (int i = 0; i < 8; ++i) {
            float4 o = make_float4(acc[i][0], acc[i][1], acc[i][2], acc[i][3]);
            *(float4*)(Out + (size_t)(warp * 8 + i) * DD + lane * 4) = o;
        }
        return;
    }

    // ---------------- topk: 8 warps x 2 rows, single-pass static threshold ----------------
    TopkS& S = *reinterpret_cast<TopkS*>(smem_raw);
    int tb = bid - bid / 5 - 1;           // 0..1535
    int rowg0 = tb * 16 + warp * 2;       // even; rows rowg0, rowg0+1 share a pair
    int pair = rowg0 / NN, n0 = rowg0 % NN;
    int p = pair / 3, qm = pair % 3;
    int q = qm + (qm >= p ? 1 : 0);
    const float4* rA = (const float4*)
        (C + (((size_t)p * VV + q) * NN + n0) * (size_t)NN);
    const float4* rB = rA + (NN / 4);

    unsigned int lmask = (1u << lane) - 1u;
    int nchA = 0, nchB = 0;

    // single pass: stream both rows, chunk-granular candidate capture
#pragma unroll
    for (int i = 0; i < 16; ++i) {
        float4 a = rA[lane + (i << 5)];
        float4 b = rB[lane + (i << 5)];
        int mb = (lane + (i << 5)) << 2;

        float ma = fmaxf(fmaxf(a.x, a.y), fmaxf(a.z, a.w));
        bool hitA = (ma >= TAU0);
        unsigned int balA = __ballot_sync(0xffffffffu, hitA);
        if (hitA) {
            int pos = (nchA + __popc(balA & lmask)) * 4;
            if (pos <= CAP - 4) {
                ulonglong2* d = (ulonglong2*)&S.cbuf[warp][0][pos];
                d[0] = make_ulonglong2(tk_key(a.x, mb + 0), tk_key(a.y, mb + 1));
                d[1] = make_ulonglong2(tk_key(a.z, mb + 2), tk_key(a.w, mb + 3));
            }
        }
        nchA += __popc(balA);

        float mbv = fmaxf(fmaxf(b.x, b.y), fmaxf(b.z, b.w));
        bool hitB = (mbv >= TAU0);
        unsigned int balB = __ballot_sync(0xffffffffu, hitB);
        if (hitB) {
            int pos = (nchB + __popc(balB & lmask)) * 4;
            if (pos <= CAP - 4) {
                ulonglong2* d = (ulonglong2*)&S.cbuf[warp][1][pos];
                d[0] = make_ulonglong2(tk_key(b.x, mb + 0), tk_key(b.y, mb + 1));
                d[1] = make_ulonglong2(tk_key(b.z, mb + 2), tk_key(b.w, mb + 3));
            }
        }
        nchB += __popc(balB);
    }
    __syncwarp();

    const unsigned int tau_hi = __float_as_uint(TAU0) | 0x80000000u;

#pragma unroll
    for (int rr = 0; rr < 2; ++rr) {
        int nslots = (rr == 0 ? nchA : nchB) * 4;
        int* outp = g_idx + (size_t)(rowg0 + rr) * KK;
        bool ok = (nslots <= CAP);
        if (ok) {
            unsigned long long k0 = (lane       < nslots) ? S.cbuf[warp][rr][lane]       : 0ull;
            unsigned long long k1 = (lane + 32  < nslots) ? S.cbuf[warp][rr][lane + 32]  : 0ull;
            unsigned long long k2 = (lane + 64  < nslots) ? S.cbuf[warp][rr][lane + 64]  : 0ull;
            unsigned long long k3 = (lane + 96  < nslots) ? S.cbuf[warp][rr][lane + 96]  : 0ull;
            unsigned long long k4 = (lane + 128 < nslots) ? S.cbuf[warp][rr][lane + 128] : 0ull;
            unsigned long long cand = k0;
            if (k1 > cand) cand = k1;
            if (k2 > cand) cand = k2;
            if (k3 > cand) cand = k3;
            if (k4 > cand) cand = k4;
            unsigned long long m = 0ull;
#pragma unroll
            for (int r = 0; r < KK; ++r) {
                m = wmax64(cand);
                if (lane == 0) outp[r] = NN - 1 - (int)(m & 0xffffffffu);
                if (cand == m) {            // unique keys: exactly one lane
                    if      (k0 == m) k0 = 0ull;
                    else if (k1 == m) k1 = 0ull;
                    else if (k2 == m) k2 = 0ull;
                    else if (k3 == m) k3 = 0ull;
                    else              k4 = 0ull;
                    cand = k0;
                    if (k1 > cand) cand = k1;
                    if (k2 > cand) cand = k2;
                    if (k3 > cand) cand = k3;
                    if (k4 > cand) cand = k4;
                }
            }
            // exact iff the 10th extracted value >= TAU0 (then >=10 elements
            // >= TAU0 exist, and ALL elements >= TAU0 were captured)
            ok = ((unsigned int)(m >> 32) >= tau_hi);
        }
        if (!ok) topk_fallback(rr == 0 ? rA : rB, lane, outp);
    }
}

// ---------------- meanV: column sums of g_V per view ----------------
__global__ void meanv_kernel()
{
    int p = blockIdx.x >> 4;
    int chunk = blockIdx.x & 15;
    int d = threadIdx.x;
    const float* base = g_V + ((size_t)p * NN + (size_t)chunk * 128) * DD + d;
    float s = 0.f;
#pragma unroll 8
    for (int r = 0; r < 128; ++r) s += base[(size_t)r * DD];
    atomicAdd((float*)&g_meanV4[0] + p * DD + d, s);
}

// ---------------- gather + sparse softmax + aggregate (vectorized) ----------------
__global__ __launch_bounds__(128) void gather_kernel(float* __restrict__ out)
{
    int n = blockIdx.x, p = blockIdx.y;
    int tid = threadIdx.x;
    int w = tid >> 5, lane = tid & 31;

    __shared__ float4 qs4[32];
    __shared__ int    sidx[32];
    __shared__ float  sc[32];
    __shared__ float  sw[32];
    __shared__ float  smax[4], ssum[4];
    __shared__ float4 part[4][32];

    if (w == 0)
        qs4[lane] = ((const float4*)g_Q)[((size_t)p * NN + n) * 32 + lane];
    if (tid >= 32 && tid < 32 + 3 * KK) {
        int t = tid - 32;
        int pair = p * 3 + t / KK;
        sidx[t] = g_idx[((size_t)pair * NN + n) * KK + (t % KK)];
    }
    __syncthreads();

    float4 q4 = qs4[lane];
    for (int t = w; t < 3 * KK; t += 4) {
        int qm = t / KK;
        int q = qm + (qm >= p ? 1 : 0);
        int m = sidx[t];
        float4 k4 = __ldg(((const float4*)g_K) + ((size_t)q * NN + m) * 32 + lane);
        float s = q4.x * k4.x + q4.y * k4.y + q4.z * k4.z + q4.w * k4.w;
#pragma unroll
        for (int off = 16; off > 0; off >>= 1)
            s += __shfl_xor_sync(0xffffffffu, s, off);
        if (lane == 0) sc[t] = s * 0.08838834764831845f;
    }
    __syncthreads();

    if (tid < 3) {
        float m2 = -3.4e38f;
#pragma unroll
        for (int k = 0; k < KK; ++k) m2 = fmaxf(m2, sc[tid * KK + k]);
        smax[tid] = m2;
    }
    __syncthreads();
    if (tid < 3 * KK) sc[tid] = expf(sc[tid] - smax[tid / KK]);
    __syncthreads();
    if (tid < 3) {
        float su = 0.f;
#pragma unroll
        for (int k = 0; k < KK; ++k) su += sc[tid * KK + k];
        ssum[tid] = su;
    }
    __syncthreads();
    if (tid < 3 * KK) sw[tid] = sc[tid] / ssum[tid / KK];
    __syncthreads();

    float4 acc = make_float4(0.f, 0.f, 0.f, 0.f);
    for (int t = w; t < 3 * KK; t += 4) {
        int qm = t / KK;
        int q = qm + (qm >= p ? 1 : 0);
        float4 v4 = __ldg(((const float4*)g_V) + ((size_t)q * NN + sidx[t]) * 32 + lane);
        float wt = sw[t];
        acc.x += wt * v4.x; acc.y += wt * v4.y;
        acc.z += wt * v4.z; acc.w += wt * v4.w;
    }
    part[w][lane] = acc;
    __syncthreads();

    if (w == 0) {
        float4 a0 = part[0][lane], a1 = part[1][lane];
        float4 a2 = part[2][lane], a3 = part[3][lane];
        float4 mv = g_meanV4[p * 32 + lane];
        const float inv = 1.0f / NN;
        float4 o;
        o.x = a0.x + a1.x + a2.x + a3.x + mv.x * inv;
        o.y = a0.y + a1.y + a2.y + a3.y + mv.y * inv;
        o.z = a0.z + a1.z + a2.z + a3.z + mv.z * inv;
        o.w = a0.w + a1.w + a2.w + a3.w + mv.w * inv;
        ((float4*)out)[((size_t)p * NN + n) * 32 + lane] = o;
    }
}

// ---------------- launch ----------------
extern "C" void kernel_launch(void* const* d_in, const int* in_sizes, int n_in,
                              void* d_out, int out_size)
{
    const float* aligned = (const float*)d_in[0];
    const float* C       = (const float*)d_in[1];
    const float* WQ      = (const float*)d_in[2];
    const float* WK      = (const float*)d_in[3];
    const float* WV      = (const float*)d_in[4];
    float* out = (float*)d_out;

    void* meanp = nullptr;
    cudaGetSymbolAddress(&meanp, g_meanV4);

    cudaMemsetAsync(meanp, 0, VV * DD * sizeof(float));
    proj_topk_kernel<<<TOTAL_BLOCKS, 256>>>(aligned, WQ, WK, WV, C);
    meanv_kernel<<<64, 128>>>();
    gather_kernel<<<dim3(NN, VV), 128>>>(out);
}

// round 7
// speedup vs baseline: 1.1697x; 1.0893x over previous
#include <cuda_runtime.h>
#include <math.h>

#define VV 4
#define NN 2048
#define DD 128
#define KK 10
#define NPAIR 12
#define CAP 144            // candidate key slots per row (36 chunks x 4)
#define TAU0 0.99f         // static threshold; exact fallback covers any input
#define PROJ_BLOCKS 768    // 12 mats x 64 tiles (32 rows)
#define TOPK_BLOCKS 6144   // 24576 rows / 4 per block
#define TOTAL_BLOCKS (PROJ_BLOCKS + TOPK_BLOCKS)   // 6912, 1:8 interleave

// ---------------- scratch (no allocs allowed) ----------------
__device__ float g_Q[VV * NN * DD];
__device__ float g_K[VV * NN * DD];
__device__ float g_V[VV * NN * DD];
__device__ int   g_idx[NPAIR * NN * KK];
__device__ float4 g_meanV4[VV * (DD / 4)];

// total-order 64-bit key: higher value wins; ties -> lower index (matches
// lax.top_k). C >= 0 so monotonic float map is bits | signbit.
__device__ __forceinline__ unsigned long long tk_key(float x, int m)
{
    unsigned int mb = __float_as_uint(x) | 0x80000000u;
    return ((unsigned long long)mb << 32) | (unsigned int)(NN - 1 - m);
}

__device__ __forceinline__ unsigned long long wmax64(unsigned long long k)
{
#pragma unroll
    for (int off = 16; off > 0; off >>= 1) {
        unsigned long long o = __shfl_xor_sync(0xffffffffu, k, off);
        if (o > k) k = o;
    }
    return k;
}

struct ProjS {
    float Xs[32][16];
    float Ws[16][132];
};
struct TopkS {
    float4 rb[4][512];                   // 4 rows x 8KB = 32 KB
    unsigned long long cbuf[4][CAP];     // 4.5 KB
};

// exact bounded-rescan fallback (rare), reads the smem-resident row
__device__ void topk_fallback(const float4* rp4, int lane, int* outp)
{
    unsigned long long bound = ~0ull;
    for (int r = 0; r < KK; ++r) {
        unsigned long long cand = 0ull;
        for (int i = 0; i < 16; ++i) {
            float4 v = rp4[lane + (i << 5)];
            int mb = (lane + (i << 5)) << 2;
            unsigned long long k;
            k = tk_key(v.x, mb + 0); if (k < bound && k > cand) cand = k;
            k = tk_key(v.y, mb + 1); if (k < bound && k > cand) cand = k;
            k = tk_key(v.z, mb + 2); if (k < bound && k > cand) cand = k;
            k = tk_key(v.w, mb + 3); if (k < bound && k > cand) cand = k;
        }
        unsigned long long m = wmax64(cand);
        if (lane == 0) outp[r] = NN - 1 - (int)(m & 0xffffffffu);
        bound = m;
    }
}

// ================= fused proj (+meanV) + topk =================
__global__ __launch_bounds__(128, 6) void proj_topk_kernel(
    const float* __restrict__ aligned,
    const float* __restrict__ WQ,
    const float* __restrict__ WK,
    const float* __restrict__ WV,
    const float* __restrict__ C)
{
    __shared__ __align__(16) unsigned char smem_raw[sizeof(TopkS)];
    int bid = blockIdx.x;
    int tid = threadIdx.x;
    int warp = tid >> 5, lane = tid & 31;

    if (bid % 9 == 0) {
        // ---------------- projection GEMM: 32 rows x 128 cols ----------------
        ProjS& S = *reinterpret_cast<ProjS*>(smem_raw);
        int pb = bid / 9;                 // 0..767
        int tile = pb & 63;
        int vm   = pb >> 6;               // 0..11
        int v = vm / 3, mat = vm % 3;
        const float* W = (mat == 0 ? WQ : (mat == 1 ? WK : WV)) + (size_t)v * DD * DD;
        float* Out = (mat == 0 ? g_Q : (mat == 1 ? g_K : g_V))
                     + (size_t)v * NN * DD + (size_t)tile * 32 * DD;
        const float* X = aligned + (size_t)v * NN * DD + (size_t)tile * 32 * DD;

        float acc[8][4];
#pragma unroll
        for (int i = 0; i < 8; ++i)
#pragma unroll
            for (int c = 0; c < 4; ++c) acc[i][c] = 0.f;

        for (int d0 = 0; d0 < DD; d0 += 16) {
            {
                int r = tid >> 2, f = tid & 3;
                float4 xv = *(const float4*)(X + (size_t)r * DD + d0 + f * 4);
                *(float4*)&S.Xs[r][f * 4] = xv;
            }
#pragma unroll
            for (int j = 0; j < 4; ++j) {
                int lin = tid * 4 + j;
                int e = lin >> 2, f = lin & 3;
                float4 wv = *(const float4*)(W + (size_t)e * DD + d0 + f * 4);
                S.Ws[f * 4 + 0][e] = wv.x;
                S.Ws[f * 4 + 1][e] = wv.y;
                S.Ws[f * 4 + 2][e] = wv.z;
                S.Ws[f * 4 + 3][e] = wv.w;
            }
            __syncthreads();
#pragma unroll
            for (int dd = 0; dd < 16; ++dd) {
                float4 b = *(const float4*)&S.Ws[dd][lane * 4];
#pragma unroll
                for (int i = 0; i < 8; ++i) {
                    float a = S.Xs[warp * 8 + i][dd];
                    acc[i][0] += a * b.x;
                    acc[i][1] += a * b.y;
                    acc[i][2] += a * b.z;
                    acc[i][3] += a * b.w;
                }
            }
            __syncthreads();
        }
#pragma unroll
        for (int i = 0; i < 8; ++i) {
            float4 o = make_float4(acc[i][0], acc[i][1], acc[i][2], acc[i][3]);
            *(float4*)(Out + (size_t)(warp * 8 + i) * DD + lane * 4) = o;
        }
        if (mat == 2) {
            // fused meanV: per-thread column partials over this tile's 8 rows
#pragma unroll
            for (int c = 0; c < 4; ++c) {
                float s = 0.f;
#pragma unroll
                for (int i = 0; i < 8; ++i) s += acc[i][c];
                atomicAdd((float*)&g_meanV4[0] + v * DD + lane * 4 + c, s);
            }
        }
        return;
    }

    // ---------------- topk: 4 warps x 1 row, cp.async-staged ----------------
    TopkS& S = *reinterpret_cast<TopkS*>(smem_raw);
    int tb = bid - bid / 9 - 1;           // 0..6143
    int rowg = tb * 4 + warp;             // 0..24575
    int pair = rowg / NN, n = rowg % NN;
    int p = pair / 3, qm = pair % 3;
    int q = qm + (qm >= p ? 1 : 0);
    const float4* rowp4 = (const float4*)
        (C + (((size_t)p * VV + q) * NN + n) * (size_t)NN);

    // stage the whole 8KB row via cp.async (deep MLP, zero reg pressure)
#pragma unroll
    for (int i = 0; i < 16; ++i) {
        int c = lane + (i << 5);
        unsigned int sa = (unsigned int)__cvta_generic_to_shared(&S.rb[warp][c]);
        asm volatile("cp.async.cg.shared.global [%0], [%1], 16;"
                     :: "r"(sa), "l"(rowp4 + c));
    }
    asm volatile("cp.async.commit_group;");
    asm volatile("cp.async.wait_group 0;" ::: "memory");
    __syncwarp();

    // single pass over smem row: chunk-granular candidate capture
    unsigned int lmask = (1u << lane) - 1u;
    int nch = 0;
#pragma unroll
    for (int i = 0; i < 16; ++i) {
        float4 a = S.rb[warp][lane + (i << 5)];
        int mb = (lane + (i << 5)) << 2;
        float ma = fmaxf(fmaxf(a.x, a.y), fmaxf(a.z, a.w));
        bool hit = (ma >= TAU0);
        unsigned int bal = __ballot_sync(0xffffffffu, hit);
        if (hit) {
            int pos = (nch + __popc(bal & lmask)) * 4;
            if (pos <= CAP - 4) {
                ulonglong2* d = (ulonglong2*)&S.cbuf[warp][pos];
                d[0] = make_ulonglong2(tk_key(a.x, mb + 0), tk_key(a.y, mb + 1));
                d[1] = make_ulonglong2(tk_key(a.z, mb + 2), tk_key(a.w, mb + 3));
            }
        }
        nch += __popc(bal);
    }
    __syncwarp();

    const unsigned int tau_hi = __float_as_uint(TAU0) | 0x80000000u;
    int nslots = nch * 4;
    int* outp = g_idx + (size_t)rowg * KK;
    bool ok = (nslots <= CAP);
    if (ok) {
        unsigned long long k0 = (lane       < nslots) ? S.cbuf[warp][lane]       : 0ull;
        unsigned long long k1 = (lane + 32  < nslots) ? S.cbuf[warp][lane + 32]  : 0ull;
        unsigned long long k2 = (lane + 64  < nslots) ? S.cbuf[warp][lane + 64]  : 0ull;
        unsigned long long k3 = (lane + 96  < nslots) ? S.cbuf[warp][lane + 96]  : 0ull;
        unsigned long long k4 = (lane + 128 < nslots) ? S.cbuf[warp][lane + 128] : 0ull;
        unsigned long long cand = k0;
        if (k1 > cand) cand = k1;
        if (k2 > cand) cand = k2;
        if (k3 > cand) cand = k3;
        if (k4 > cand) cand = k4;
        unsigned long long m = 0ull;
#pragma unroll
        for (int r = 0; r < KK; ++r) {
            m = wmax64(cand);
            if (lane == 0) outp[r] = NN - 1 - (int)(m & 0xffffffffu);
            if (cand == m) {                // unique keys: exactly one lane
                if      (k0 == m) k0 = 0ull;
                else if (k1 == m) k1 = 0ull;
                else if (k2 == m) k2 = 0ull;
                else if (k3 == m) k3 = 0ull;
                else              k4 = 0ull;
                cand = k0;
                if (k1 > cand) cand = k1;
                if (k2 > cand) cand = k2;
                if (k3 > cand) cand = k3;
                if (k4 > cand) cand = k4;
            }
        }
        // exact iff 10th extracted value >= TAU0 (all >=TAU0 were captured)
        ok = ((unsigned int)(m >> 32) >= tau_hi);
    }
    if (!ok) topk_fallback(S.rb[warp], lane, outp);
}

// ---------------- gather + sparse softmax + aggregate (vectorized) ----------------
__global__ __launch_bounds__(128) void gather_kernel(float* __restrict__ out)
{
    int n = blockIdx.x, p = blockIdx.y;
    int tid = threadIdx.x;
    int w = tid >> 5, lane = tid & 31;

    __shared__ float4 qs4[32];
    __shared__ int    sidx[32];
    __shared__ float  sc[32];
    __shared__ float  sw[32];
    __shared__ float  smax[4], ssum[4];
    __shared__ float4 part[4][32];

    if (w == 0)
        qs4[lane] = ((const float4*)g_Q)[((size_t)p * NN + n) * 32 + lane];
    if (tid >= 32 && tid < 32 + 3 * KK) {
        int t = tid - 32;
        int pair = p * 3 + t / KK;
        sidx[t] = g_idx[((size_t)pair * NN + n) * KK + (t % KK)];
    }
    __syncthreads();

    float4 q4 = qs4[lane];
    for (int t = w; t < 3 * KK; t += 4) {
        int qm = t / KK;
        int q = qm + (qm >= p ? 1 : 0);
        int m = sidx[t];
        float4 k4 = __ldg(((const float4*)g_K) + ((size_t)q * NN + m) * 32 + lane);
        float s = q4.x * k4.x + q4.y * k4.y + q4.z * k4.z + q4.w * k4.w;
#pragma unroll
        for (int off = 16; off > 0; off >>= 1)
            s += __shfl_xor_sync(0xffffffffu, s, off);
        if (lane == 0) sc[t] = s * 0.08838834764831845f;
    }
    __syncthreads();

    if (tid < 3) {
        float m2 = -3.4e38f;
#pragma unroll
        for (int k = 0; k < KK; ++k) m2 = fmaxf(m2, sc[tid * KK + k]);
        smax[tid] = m2;
    }
    __syncthreads();
    if (tid < 3 * KK) sc[tid] = expf(sc[tid] - smax[tid / KK]);
    __syncthreads();
    if (tid < 3) {
        float su = 0.f;
#pragma unroll
        for (int k = 0; k < KK; ++k) su += sc[tid * KK + k];
        ssum[tid] = su;
    }
    __syncthreads();
    if (tid < 3 * KK) sw[tid] = sc[tid] / ssum[tid / KK];
    __syncthreads();

    float4 acc = make_float4(0.f, 0.f, 0.f, 0.f);
    for (int t = w; t < 3 * KK; t += 4) {
        int qm = t / KK;
        int q = qm + (qm >= p ? 1 : 0);
        float4 v4 = __ldg(((const float4*)g_V) + ((size_t)q * NN + sidx[t]) * 32 + lane);
        float wt = sw[t];
        acc.x += wt * v4.x; acc.y += wt * v4.y;
        acc.z += wt * v4.z; acc.w += wt * v4.w;
    }
    part[w][lane] = acc;
    __syncthreads();

    if (w == 0) {
        float4 a0 = part[0][lane], a1 = part[1][lane];
        float4 a2 = part[2][lane], a3 = part[3][lane];
        float4 mv = g_meanV4[p * 32 + lane];
        const float inv = 1.0f / NN;
        float4 o;
        o.x = a0.x + a1.x + a2.x + a3.x + mv.x * inv;
        o.y = a0.y + a1.y + a2.y + a3.y + mv.y * inv;
        o.z = a0.z + a1.z + a2.z + a3.z + mv.z * inv;
        o.w = a0.w + a1.w + a2.w + a3.w + mv.w * inv;
        ((float4*)out)[((size_t)p * NN + n) * 32 + lane] = o;
    }
}

// ---------------- launch ----------------
extern "C" void kernel_launch(void* const* d_in, const int* in_sizes, int n_in,
                              void* d_out, int out_size)
{
    const float* aligned = (const float*)d_in[0];
    const float* C       = (const float*)d_in[1];
    const float* WQ      = (const float*)d_in[2];
    const float* WK      = (const float*)d_in[3];
    const float* WV      = (const float*)d_in[4];
    float* out = (float*)d_out;

    void* meanp = nullptr;
    cudaGetSymbolAddress(&meanp, g_meanV4);

    cudaMemsetAsync(meanp, 0, VV * DD * sizeof(float));
    proj_topk_kernel<<<TOTAL_BLOCKS, 128>>>(aligned, WQ, WK, WV, C);
    gather_kernel<<<dim3(NN, VV), 128>>>(out);
}